// round 17
// baseline (speedup 1.0000x reference)
#include <cuda_runtime.h>
#include <cstdint>

#define B_     2
#define NRES   2048
#define NATOM  16384
#define CS     384
#define COUT   50
#define OPAD   64
#define KT     96                            // 4 K-tile rounds (was 6)
#define RPB    16                            // rows per GEMM block
#define GEMM_BLOCKS ((B_ * NRES) / RPB)      // 256
#define K1_ATOMS    22528                    // scanned in K1 (0.6875 of total)
#define K2_ATOMS    (B_ * NATOM - K1_ATOMS)  // 10240
#define SCAN1_BLOCKS (K1_ATOMS / 8)          // 2816
#define GATH_BLOCKS  (K1_ATOMS / 64)         // 352 (8 atoms/warp, 8 warps)
#define SCAN2_BLOCKS (K2_ATOMS / 8)          // 1280

// Scratch
__device__ float g_res_logits[B_ * NRES * COUT];   // 3.2 MB (L2-resident)
__device__ int   g_idx[K1_ATOMS];                  // 88 KB

// ---------------------------------------------------------------------------
// K1: blocks [0,256)       GEMM res_logits = s @ W^T + b  (4 rounds of KT=96)
//     blocks [256,3072)    scan atoms [0, 22528) -> g_idx  (1 atom/warp)
// ---------------------------------------------------------------------------
__global__ void __launch_bounds__(256)
k1_gemm_scan(const float* __restrict__ s,     // [B, NRES, CS]
             const float* __restrict__ tta,   // [B, NATOM, NRES]
             const float* __restrict__ W,     // [COUT, CS]
             const float* __restrict__ bias)  // [COUT]
{
    __shared__ float s_sm[RPB][KT];     // 6 KB
    __shared__ float wt_sm[KT][OPAD];   // 24 KB (30 KB total -> 6 blocks/SM)

    const int tid = threadIdx.x;

    if (blockIdx.x < GEMM_BLOCKS) {
        // ----------------- GEMM branch: 16 rows, 1 row x 4 outs/thread -----
        const int to  = tid & 15;
        const int tr  = tid >> 4;
        const int o0  = to << 2;
        const int row0 = blockIdx.x * RPB;

        const int wo = tid & 63;          // out channel for W transpose loads
        const int wg = tid >> 6;          // k-group 0..3 (24 k each)

        float4 acc = make_float4(0.f, 0.f, 0.f, 0.f);

        for (int kt = 0; kt < CS; kt += KT) {          // 4 rounds
            // s tile: 16 rows x 96 k = 384 float4 (24 f4 per row)
            {
                const float4* __restrict__ sg = reinterpret_cast<const float4*>(s);
                float4* s4 = reinterpret_cast<float4*>(&s_sm[0][0]);
                {
                    const int r = tid / 24, c = tid - r * 24;
                    s4[tid] = sg[(size_t)(row0 + r) * (CS / 4) + (kt >> 2) + c];
                }
                if (tid < 128) {
                    const int f = tid + 256;
                    const int r = f / 24, c = f - r * 24;
                    s4[f] = sg[(size_t)(row0 + r) * (CS / 4) + (kt >> 2) + c];
                }
            }
            // W tile transposed: thread (wg,wo) covers k in [wg*24, wg*24+24)
            #pragma unroll
            for (int m = 0; m < 6; ++m) {
                const int k0 = wg * 24 + (m << 2);
                float4 v = make_float4(0.f, 0.f, 0.f, 0.f);
                if (wo < COUT)
                    v = *reinterpret_cast<const float4*>(&W[(size_t)wo * CS + kt + k0]);
                wt_sm[k0 + 0][wo] = v.x;
                wt_sm[k0 + 1][wo] = v.y;
                wt_sm[k0 + 2][wo] = v.z;
                wt_sm[k0 + 3][wo] = v.w;
            }
            __syncthreads();

            #pragma unroll
            for (int kk = 0; kk < KT; kk += 4) {       // 24 iterations
                const float4 sa = *reinterpret_cast<const float4*>(&s_sm[tr][kk]);
                const float4 w0 = *reinterpret_cast<const float4*>(&wt_sm[kk + 0][o0]);
                const float4 w1 = *reinterpret_cast<const float4*>(&wt_sm[kk + 1][o0]);
                const float4 w2 = *reinterpret_cast<const float4*>(&wt_sm[kk + 2][o0]);
                const float4 w3 = *reinterpret_cast<const float4*>(&wt_sm[kk + 3][o0]);

                acc.x = fmaf(sa.x, w0.x, acc.x); acc.y = fmaf(sa.x, w0.y, acc.y);
                acc.z = fmaf(sa.x, w0.z, acc.z); acc.w = fmaf(sa.x, w0.w, acc.w);
                acc.x = fmaf(sa.y, w1.x, acc.x); acc.y = fmaf(sa.y, w1.y, acc.y);
                acc.z = fmaf(sa.y, w1.z, acc.z); acc.w = fmaf(sa.y, w1.w, acc.w);
                acc.x = fmaf(sa.z, w2.x, acc.x); acc.y = fmaf(sa.z, w2.y, acc.y);
                acc.z = fmaf(sa.z, w2.z, acc.z); acc.w = fmaf(sa.z, w2.w, acc.w);
                acc.x = fmaf(sa.w, w3.x, acc.x); acc.y = fmaf(sa.w, w3.y, acc.y);
                acc.z = fmaf(sa.w, w3.z, acc.z); acc.w = fmaf(sa.w, w3.w, acc.w);
            }
            __syncthreads();
        }

        const float a4[4] = {acc.x, acc.y, acc.z, acc.w};
        #pragma unroll
        for (int c = 0; c < 4; ++c) {
            const int o = o0 + c;
            if (o < COUT)
                g_res_logits[(size_t)(row0 + tr) * COUT + o] = a4[c] + bias[o];
        }
    } else {
        // -------- scan atoms [0, 22528): 1 atom/warp, MLP=4 --------
        const int gwarp = (blockIdx.x - GEMM_BLOCKS) * 8 + (tid >> 5);
        const int lane  = tid & 31;

        const float4* __restrict__ row =
            reinterpret_cast<const float4*>(tta + (size_t)gwarp * NRES);

        int idx = 0;
        #pragma unroll 1
        for (int r = 0; r < 4; ++r) {
            float4 v[4];
            #pragma unroll
            for (int j = 0; j < 4; ++j)
                v[j] = __ldcs(&row[r * 128 + j * 32 + lane]);

            int my = -1;
            #pragma unroll
            for (int j = 3; j >= 0; --j) {
                const int jb = (r * 128 + j * 32 + lane) << 2;
                if (v[j].w != 0.0f) my = jb + 3;
                if (v[j].z != 0.0f) my = jb + 2;
                if (v[j].y != 0.0f) my = jb + 1;
                if (v[j].x != 0.0f) my = jb;
            }

            const unsigned m = __ballot_sync(0xffffffffu, my >= 0);
            if (m) {
                idx = __shfl_sync(0xffffffffu, my, __ffs(m) - 1);
                break;
            }
        }

        if (lane == 0) g_idx[gwarp] = idx;
    }
}

// ---------------------------------------------------------------------------
// K2: blocks [0,352)       gather K1's 22528 atoms (8 atoms/warp; hidden)
//     blocks [352,1632)    scan atoms [22528, 32768) with inline gather
// ---------------------------------------------------------------------------
__global__ void __launch_bounds__(256)
k2_gather_scan(const float* __restrict__ tta,   // [B, NATOM, NRES]
               float* __restrict__ out)         // [B, NATOM, COUT]
{
    const int tid  = threadIdx.x;
    const int lane = tid & 31;

    if (blockIdx.x < GATH_BLOCKS) {
        // -------- gather branch: 8 atoms/warp --------
        const int gw = blockIdx.x * 8 + (tid >> 5);   // 0..2815
        const int a0 = gw * 8;                        // 0..22520

        int myv = 0;
        if (lane < 8) myv = g_idx[a0 + lane];

        const int b = a0 >> 14;                       // no straddle (8 | 16384)
        const float* __restrict__ base = g_res_logits + (size_t)b * NRES * COUT;

        const float2* src[8];
        #pragma unroll
        for (int j = 0; j < 8; ++j) {
            const int ij = __shfl_sync(0xffffffffu, myv, j);
            src[j] = reinterpret_cast<const float2*>(base + (size_t)ij * COUT);
        }

        if (lane < COUT / 2) {
            float2 x[8];
            #pragma unroll
            for (int j = 0; j < 8; ++j)
                x[j] = src[j][lane];
            float2* __restrict__ d =
                reinterpret_cast<float2*>(out + (size_t)a0 * COUT);
            #pragma unroll
            for (int j = 0; j < 8; ++j)
                d[lane + 25 * j] = x[j];              // 25 float2 per atom
        }
    } else {
        // -------- scan atoms [22528, 32768) + inline gather --------
        const int gwarp = K1_ATOMS + (blockIdx.x - GATH_BLOCKS) * 8 + (tid >> 5);

        const float4* __restrict__ row =
            reinterpret_cast<const float4*>(tta + (size_t)gwarp * NRES);

        int idx = 0;
        #pragma unroll 1
        for (int r = 0; r < 4; ++r) {
            float4 v[4];
            #pragma unroll
            for (int j = 0; j < 4; ++j)
                v[j] = __ldcs(&row[r * 128 + j * 32 + lane]);

            int my = -1;
            #pragma unroll
            for (int j = 3; j >= 0; --j) {
                const int jb = (r * 128 + j * 32 + lane) << 2;
                if (v[j].w != 0.0f) my = jb + 3;
                if (v[j].z != 0.0f) my = jb + 2;
                if (v[j].y != 0.0f) my = jb + 1;
                if (v[j].x != 0.0f) my = jb;
            }

            const unsigned m = __ballot_sync(0xffffffffu, my >= 0);
            if (m) {
                idx = __shfl_sync(0xffffffffu, my, __ffs(m) - 1);
                break;
            }
        }

        // inline gather (proven ~free): 25 lanes x float2
        const int b = gwarp >> 14;
        const float2* __restrict__ src = reinterpret_cast<const float2*>(
            g_res_logits + ((size_t)b * NRES + idx) * COUT);
        float2* __restrict__ dst = reinterpret_cast<float2*>(
            out + (size_t)gwarp * COUT);
        if (lane < COUT / 2) dst[lane] = src[lane];
    }
}

extern "C" void kernel_launch(void* const* d_in, const int* in_sizes, int n_in,
                              void* d_out, int out_size)
{
    const float* s    = (const float*)d_in[0];  // [B, NRES, CS]
    const float* tta  = (const float*)d_in[1];  // [B, NATOM, NRES]
    const float* W    = (const float*)d_in[2];  // [COUT, CS]
    const float* bias = (const float*)d_in[3];  // [COUT]
    float* out = (float*)d_out;

    (void)in_sizes; (void)n_in; (void)out_size;

    k1_gemm_scan<<<GEMM_BLOCKS + SCAN1_BLOCKS, 256>>>(s, tta, W, bias);
    k2_gather_scan<<<GATH_BLOCKS + SCAN2_BLOCKS, 256>>>(tta, out);
}